// round 3
// baseline (speedup 1.0000x reference)
#include <cuda_runtime.h>
#include <cuda_bf16.h>
#include <math.h>

// Problem constants
#define BB 2
#define SS 2048
#define HH 4096
#define NHH 32
#define HD 128
#define TOK (BB*SS)          // 4096
#define QKVD (3*HH)          // 12288

// ---------------------------------------------------------------------------
// Scratch (device globals; no allocations allowed)
// ---------------------------------------------------------------------------
__device__ float g_qkv[(size_t)TOK * QKVD];            // 201 MB
__device__ float g_q  [(size_t)BB * NHH * SS * HD];    // 67 MB
__device__ float g_k  [(size_t)BB * NHH * SS * HD];    // 67 MB
__device__ float g_v  [(size_t)BB * NHH * SS * HD];    // 67 MB
__device__ float g_ao [(size_t)TOK * HH];              // 67 MB

// ---------------------------------------------------------------------------
// SGEMM (NT): C[M,N] = A[M,K] * B[N,K]^T, all row-major, fp32.
// 128x128 block tile, BK=16, 256 threads, 8x8 per thread.
// Double-buffered smem; global loads register-staged so tile k+1's LDGs
// overlap tile k's FFMAs. One __syncthreads per tile.
// M,N,K all multiples of 128/16 here -> no bounds checks.
// ---------------------------------------------------------------------------
#define BM 128
#define BN 128
#define BK 16

__global__ __launch_bounds__(256) void sgemm_nt(const float* __restrict__ A,
                                                const float* __restrict__ B,
                                                float* __restrict__ C,
                                                int M, int N, int K)
{
    __shared__ float As[2][BK][BM];
    __shared__ float Bs[2][BK][BN];

    const int tid  = threadIdx.x;
    const int tRow = tid >> 4;    // 0..15
    const int tCol = tid & 15;    // 0..15
    const size_t rowBase = (size_t)blockIdx.y * BM;
    const size_t colBase = (size_t)blockIdx.x * BN;

    // loader: each thread loads 2 float4 per tile per matrix
    const int la_row = tid >> 2;        // 0..63
    const int la_col = (tid & 3) * 4;   // 0,4,8,12

    const float* Aptr = A + rowBase * (size_t)K;
    const float* Bptr = B + colBase * (size_t)K;

    float acc[8][8];
    #pragma unroll
    for (int i = 0; i < 8; i++)
        #pragma unroll
        for (int j = 0; j < 8; j++) acc[i][j] = 0.f;

    float4 ra0, ra1, rb0, rb1;

    // prologue: load tile 0 into buffer 0
    ra0 = *(const float4*)(Aptr + (size_t)(la_row     ) * K + la_col);
    ra1 = *(const float4*)(Aptr + (size_t)(la_row + 64) * K + la_col);
    rb0 = *(const float4*)(Bptr + (size_t)(la_row     ) * K + la_col);
    rb1 = *(const float4*)(Bptr + (size_t)(la_row + 64) * K + la_col);

    As[0][la_col + 0][la_row]      = ra0.x;
    As[0][la_col + 1][la_row]      = ra0.y;
    As[0][la_col + 2][la_row]      = ra0.z;
    As[0][la_col + 3][la_row]      = ra0.w;
    As[0][la_col + 0][la_row + 64] = ra1.x;
    As[0][la_col + 1][la_row + 64] = ra1.y;
    As[0][la_col + 2][la_row + 64] = ra1.z;
    As[0][la_col + 3][la_row + 64] = ra1.w;
    Bs[0][la_col + 0][la_row]      = rb0.x;
    Bs[0][la_col + 1][la_row]      = rb0.y;
    Bs[0][la_col + 2][la_row]      = rb0.z;
    Bs[0][la_col + 3][la_row]      = rb0.w;
    Bs[0][la_col + 0][la_row + 64] = rb1.x;
    Bs[0][la_col + 1][la_row + 64] = rb1.y;
    Bs[0][la_col + 2][la_row + 64] = rb1.z;
    Bs[0][la_col + 3][la_row + 64] = rb1.w;
    __syncthreads();

    int buf = 0;
    for (int kb = 0; kb < K; kb += BK) {
        const int nxt = kb + BK;
        const bool has_next = (nxt < K);

        // issue next tile's global loads early (overlap with compute below)
        if (has_next) {
            ra0 = *(const float4*)(Aptr + (size_t)(la_row     ) * K + nxt + la_col);
            ra1 = *(const float4*)(Aptr + (size_t)(la_row + 64) * K + nxt + la_col);
            rb0 = *(const float4*)(Bptr + (size_t)(la_row     ) * K + nxt + la_col);
            rb1 = *(const float4*)(Bptr + (size_t)(la_row + 64) * K + nxt + la_col);
        }

        // compute current tile
        #pragma unroll
        for (int kk = 0; kk < BK; kk++) {
            float rm[8], rn[8];
            *(float4*)(rm + 0) = *(const float4*)&As[buf][kk][tRow * 8 + 0];
            *(float4*)(rm + 4) = *(const float4*)&As[buf][kk][tRow * 8 + 4];
            *(float4*)(rn + 0) = *(const float4*)&Bs[buf][kk][tCol * 8 + 0];
            *(float4*)(rn + 4) = *(const float4*)&Bs[buf][kk][tCol * 8 + 4];
            #pragma unroll
            for (int i = 0; i < 8; i++)
                #pragma unroll
                for (int j = 0; j < 8; j++)
                    acc[i][j] = fmaf(rm[i], rn[j], acc[i][j]);
        }

        // stage next tile into the other buffer (safe: everyone finished
        // reading buf^1 at the sync that ended the previous iteration)
        if (has_next) {
            const int nb = buf ^ 1;
            As[nb][la_col + 0][la_row]      = ra0.x;
            As[nb][la_col + 1][la_row]      = ra0.y;
            As[nb][la_col + 2][la_row]      = ra0.z;
            As[nb][la_col + 3][la_row]      = ra0.w;
            As[nb][la_col + 0][la_row + 64] = ra1.x;
            As[nb][la_col + 1][la_row + 64] = ra1.y;
            As[nb][la_col + 2][la_row + 64] = ra1.z;
            As[nb][la_col + 3][la_row + 64] = ra1.w;
            Bs[nb][la_col + 0][la_row]      = rb0.x;
            Bs[nb][la_col + 1][la_row]      = rb0.y;
            Bs[nb][la_col + 2][la_row]      = rb0.z;
            Bs[nb][la_col + 3][la_row]      = rb0.w;
            Bs[nb][la_col + 0][la_row + 64] = rb1.x;
            Bs[nb][la_col + 1][la_row + 64] = rb1.y;
            Bs[nb][la_col + 2][la_row + 64] = rb1.z;
            Bs[nb][la_col + 3][la_row + 64] = rb1.w;
            __syncthreads();
            buf = nb;
        }
    }

    #pragma unroll
    for (int i = 0; i < 8; i++) {
        size_t r = rowBase + tRow * 8 + i;
        float* crow = C + r * (size_t)N + colBase + tCol * 8;
        float4 v0 = make_float4(acc[i][0], acc[i][1], acc[i][2], acc[i][3]);
        float4 v1 = make_float4(acc[i][4], acc[i][5], acc[i][6], acc[i][7]);
        *(float4*)(crow + 0) = v0;
        *(float4*)(crow + 4) = v1;
    }
}

// ---------------------------------------------------------------------------
// RoPE + split/transpose: g_qkv [tok][12288] -> g_q/g_k/g_v [b,h,s,d]
// grid (NH, S, B), 64 threads (one per rotation pair)
// ---------------------------------------------------------------------------
__global__ void rope_kernel(const int* __restrict__ pos)
{
    const int h = blockIdx.x;
    const int s = blockIdx.y;
    const int b = blockIdx.z;
    const int d = threadIdx.x;          // 0..63

    const size_t tok = (size_t)b * SS + s;
    const float* base = g_qkv + tok * QKVD + (size_t)h * HD;
    const float p = (float)pos[tok];

    // inv_freq = 10000^(-d/64) ; log2(10000) = 13.287712379549449
    const float c0 = 13.287712379549449f / 64.f;
    float ang = p * exp2f(-(float)d * c0);
    float cs, sn;
    sincosf(ang, &sn, &cs);

    const size_t oidx = (((size_t)(b * NHH + h)) * SS + s) * HD;

    // q
    float x1 = base[d], x2 = base[d + 64];
    g_q[oidx + d]      = x1 * cs - x2 * sn;
    g_q[oidx + d + 64] = x2 * cs + x1 * sn;
    // k
    x1 = base[HH + d]; x2 = base[HH + d + 64];
    g_k[oidx + d]      = x1 * cs - x2 * sn;
    g_k[oidx + d + 64] = x2 * cs + x1 * sn;
    // v (plain copy)
    g_v[oidx + d]      = base[2 * HH + d];
    g_v[oidx + d + 64] = base[2 * HH + d + 64];
}

// ---------------------------------------------------------------------------
// fp32 causal flash attention.
// Block = 64 q-rows of one (b,h). 256 threads as 16x16:
//   thread(ty,tx): output rows ty*4..+3, output cols tx*8..+7
//   score tile 64x64: thread computes rows ty*4..+3, cols tx*4..+3
// smem (dynamic): Qs[64][132] + KVs[64][132] + Ps[64][68]  = 84992 bytes
// ---------------------------------------------------------------------------
#define ATTN_SMEM_BYTES ((64*132*2 + 64*68) * 4)

__global__ __launch_bounds__(256) void attn_kernel(void)
{
    extern __shared__ float sm[];
    float* Qs  = sm;                 // [64][132]
    float* KVs = sm + 64 * 132;      // [64][132]  (K, then reused for V)
    float* Ps  = sm + 2 * 64 * 132;  // [64][68]

    const int qt = blockIdx.x;
    const int h  = blockIdx.y;
    const int b  = blockIdx.z;
    const int tid = threadIdx.x;
    const int ty  = tid >> 4;   // 0..15
    const int tx  = tid & 15;   // 0..15

    const size_t headBase = ((size_t)(b * NHH + h)) * SS * HD;
    const float* Qg = g_q + headBase + (size_t)qt * 64 * HD;
    const float* Kg = g_k + headBase;
    const float* Vg = g_v + headBase;

    // load Q tile (64x128)
    for (int idx = tid; idx < 64 * 32; idx += 256) {
        int r = idx >> 5, c4 = idx & 31;
        *(float4*)(Qs + r * 132 + c4 * 4) = *(const float4*)(Qg + (size_t)r * HD + c4 * 4);
    }

    float o[4][8];
    float m[4], l[4];
    #pragma unroll
    for (int r = 0; r < 4; r++) {
        m[r] = -1e30f; l[r] = 0.f;
        #pragma unroll
        for (int c = 0; c < 8; c++) o[r][c] = 0.f;
    }

    const int qi0 = qt * 64;
    const float scale = 0.08838834764831845f;   // 1/sqrt(128)

    for (int jt = 0; jt <= qt; jt++) {
        __syncthreads();   // protect KVs/Ps from previous iteration readers
        // load K tile
        for (int idx = tid; idx < 64 * 32; idx += 256) {
            int r = idx >> 5, c4 = idx & 31;
            *(float4*)(KVs + r * 132 + c4 * 4) =
                *(const float4*)(Kg + ((size_t)(jt * 64 + r)) * HD + c4 * 4);
        }
        __syncthreads();

        // scores: s[r][c] = Q[row] . K[col]
        float s[4][4];
        #pragma unroll
        for (int r = 0; r < 4; r++)
            #pragma unroll
            for (int c = 0; c < 4; c++) s[r][c] = 0.f;

        #pragma unroll 8
        for (int d = 0; d < 128; d += 4) {
            float4 qv[4], kv[4];
            #pragma unroll
            for (int r = 0; r < 4; r++) qv[r] = *(const float4*)(Qs + (ty * 4 + r) * 132 + d);
            #pragma unroll
            for (int c = 0; c < 4; c++) kv[c] = *(const float4*)(KVs + (tx * 4 + c) * 132 + d);
            #pragma unroll
            for (int r = 0; r < 4; r++)
                #pragma unroll
                for (int c = 0; c < 4; c++) {
                    s[r][c] = fmaf(qv[r].x, kv[c].x, s[r][c]);
                    s[r][c] = fmaf(qv[r].y, kv[c].y, s[r][c]);
                    s[r][c] = fmaf(qv[r].z, kv[c].z, s[r][c]);
                    s[r][c] = fmaf(qv[r].w, kv[c].w, s[r][c]);
                }
        }

        // online softmax update (per-row; 16 tx threads share a row, width-16 shfl)
        #pragma unroll
        for (int r = 0; r < 4; r++) {
            const int qi = qi0 + ty * 4 + r;
            float mloc = -1e30f;
            #pragma unroll
            for (int c = 0; c < 4; c++) {
                const int kj = jt * 64 + tx * 4 + c;
                float sv = (kj <= qi) ? s[r][c] * scale : -1e30f;
                s[r][c] = sv;
                mloc = fmaxf(mloc, sv);
            }
            #pragma unroll
            for (int off = 8; off >= 1; off >>= 1)
                mloc = fmaxf(mloc, __shfl_xor_sync(0xffffffffu, mloc, off, 16));
            const float mnew = fmaxf(m[r], mloc);
            const float corr = __expf(m[r] - mnew);
            float psum = 0.f;
            #pragma unroll
            for (int c = 0; c < 4; c++) {
                float pv = __expf(s[r][c] - mnew);
                s[r][c] = pv;
                psum += pv;
            }
            #pragma unroll
            for (int off = 8; off >= 1; off >>= 1)
                psum += __shfl_xor_sync(0xffffffffu, psum, off, 16);
            l[r] = l[r] * corr + psum;
            m[r] = mnew;
            #pragma unroll
            for (int c = 0; c < 8; c++) o[r][c] *= corr;
        }

        // stash P
        #pragma unroll
        for (int r = 0; r < 4; r++)
            #pragma unroll
            for (int c = 0; c < 4; c++)
                Ps[(ty * 4 + r) * 68 + tx * 4 + c] = s[r][c];
        __syncthreads();

        // load V over K's smem
        for (int idx = tid; idx < 64 * 32; idx += 256) {
            int r = idx >> 5, c4 = idx & 31;
            *(float4*)(KVs + r * 132 + c4 * 4) =
                *(const float4*)(Vg + ((size_t)(jt * 64 + r)) * HD + c4 * 4);
        }
        __syncthreads();

        // O += P @ V
        #pragma unroll 4
        for (int j = 0; j < 64; j++) {
            float pr[4];
            #pragma unroll
            for (int r = 0; r < 4; r++) pr[r] = Ps[(ty * 4 + r) * 68 + j];
            float4 v0 = *(const float4*)(KVs + j * 132 + tx * 8 + 0);
            float4 v1 = *(const float4*)(KVs + j * 132 + tx * 8 + 4);
            #pragma unroll
            for (int r = 0; r < 4; r++) {
                o[r][0] = fmaf(pr[r], v0.x, o[r][0]);
                o[r][1] = fmaf(pr[r], v0.y, o[r][1]);
                o[r][2] = fmaf(pr[r], v0.z, o[r][2]);
                o[r][3] = fmaf(pr[r], v0.w, o[r][3]);
                o[r][4] = fmaf(pr[r], v1.x, o[r][4]);
                o[r][5] = fmaf(pr[r], v1.y, o[r][5]);
                o[r][6] = fmaf(pr[r], v1.z, o[r][6]);
                o[r][7] = fmaf(pr[r], v1.w, o[r][7]);
            }
        }
    }

    // write out in [b, s, h*128+d] layout (ready for the final NT GEMM)
    #pragma unroll
    for (int r = 0; r < 4; r++) {
        const int s_idx = qi0 + ty * 4 + r;
        const float inv = 1.f / l[r];
        float* dst = g_ao + ((size_t)(b * SS + s_idx)) * HH + (size_t)h * HD + tx * 8;
        float4 a0 = make_float4(o[r][0] * inv, o[r][1] * inv, o[r][2] * inv, o[r][3] * inv);
        float4 a1 = make_float4(o[r][4] * inv, o[r][5] * inv, o[r][6] * inv, o[r][7] * inv);
        *(float4*)(dst + 0) = a0;
        *(float4*)(dst + 4) = a1;
    }
}

// ---------------------------------------------------------------------------
// launch
// ---------------------------------------------------------------------------
extern "C" void kernel_launch(void* const* d_in, const int* in_sizes, int n_in,
                              void* d_out, int out_size)
{
    (void)in_sizes; (void)n_in; (void)out_size;
    const float* hidden = (const float*)d_in[0];
    const int*   pos    = (const int*)  d_in[1];
    const float* w_pack = (const float*)d_in[2];
    const float* w_o    = (const float*)d_in[3];
    float* out = (float*)d_out;

    float *p_qkv, *p_ao;
    cudaGetSymbolAddress((void**)&p_qkv, g_qkv);
    cudaGetSymbolAddress((void**)&p_ao,  g_ao);

    cudaFuncSetAttribute(attn_kernel,
                         cudaFuncAttributeMaxDynamicSharedMemorySize,
                         ATTN_SMEM_BYTES);

    // 1) QKV projection: [4096 x 4096] x [12288 x 4096]^T
    {
        dim3 grid(QKVD / BN, TOK / BM);
        sgemm_nt<<<grid, 256>>>(hidden, w_pack, p_qkv, TOK, QKVD, HH);
    }

    // 2) RoPE + split/transpose
    {
        dim3 grid(NHH, SS, BB);
        rope_kernel<<<grid, 64>>>(pos);
    }

    // 3) causal flash attention
    {
        dim3 grid(SS / 64, NHH, BB);
        attn_kernel<<<grid, 256, ATTN_SMEM_BYTES>>>();
    }

    // 4) output projection: [4096 x 4096] x [4096 x 4096]^T -> d_out
    {
        dim3 grid(HH / BN, TOK / BM);
        sgemm_nt<<<grid, 256>>>(p_ao, w_o, out, TOK, HH, HH);
    }
}

// round 15
// speedup vs baseline: 1.6638x; 1.6638x over previous
#include <cuda_runtime.h>
#include <cuda_bf16.h>
#include <math.h>
#include <stdint.h>

// Problem constants
#define BB 2
#define SS 2048
#define HH 4096
#define NHH 32
#define HD 128
#define TOK (BB*SS)          // 4096
#define QKVD (3*HH)          // 12288

// ---------------------------------------------------------------------------
// Scratch (device globals; no allocations allowed)
// ---------------------------------------------------------------------------
__device__ __align__(16) float g_qkv[(size_t)TOK * QKVD];            // 201 MB
__device__ __align__(16) float g_q  [(size_t)BB * NHH * SS * HD];    // 67 MB
__device__ __align__(16) float g_k  [(size_t)BB * NHH * SS * HD];    // 67 MB
__device__ __align__(16) float g_v  [(size_t)BB * NHH * SS * HD];    // 67 MB

// bf16 hi/lo split operands for tensor-core GEMMs
__device__ __align__(16) __nv_bfloat16 g_hid_h[(size_t)TOK * HH];
__device__ __align__(16) __nv_bfloat16 g_hid_l[(size_t)TOK * HH];
__device__ __align__(16) __nv_bfloat16 g_wp_h [(size_t)QKVD * HH];
__device__ __align__(16) __nv_bfloat16 g_wp_l [(size_t)QKVD * HH];
__device__ __align__(16) __nv_bfloat16 g_wo_h [(size_t)HH * HH];
__device__ __align__(16) __nv_bfloat16 g_wo_l [(size_t)HH * HH];
__device__ __align__(16) __nv_bfloat16 g_ao_h [(size_t)TOK * HH];
__device__ __align__(16) __nv_bfloat16 g_ao_l [(size_t)TOK * HH];

// ---------------------------------------------------------------------------
// helpers
// ---------------------------------------------------------------------------
__device__ __forceinline__ uint32_t smem_u32(const void* p) {
    uint32_t a;
    asm("{ .reg .u64 t; cvta.to.shared.u64 t, %1; cvt.u32.u64 %0, t; }" : "=r"(a) : "l"(p));
    return a;
}
#define CP_ASYNC16(dst, src) \
    asm volatile("cp.async.cg.shared.global [%0], [%1], 16;" :: "r"(dst), "l"(src))
#define CP_COMMIT() asm volatile("cp.async.commit_group;" ::: "memory")

__device__ __forceinline__ void ldmatrix_x4(uint32_t& r0, uint32_t& r1,
                                            uint32_t& r2, uint32_t& r3, uint32_t addr) {
    asm volatile("ldmatrix.sync.aligned.m8n8.x4.shared.b16 {%0,%1,%2,%3}, [%4];"
                 : "=r"(r0), "=r"(r1), "=r"(r2), "=r"(r3) : "r"(addr));
}
__device__ __forceinline__ void mma_bf16(float* d, const uint32_t* a, const uint32_t* b) {
    asm volatile(
        "mma.sync.aligned.m16n8k16.row.col.f32.bf16.bf16.f32 "
        "{%0,%1,%2,%3},{%4,%5,%6,%7},{%8,%9},{%0,%1,%2,%3};"
        : "+f"(d[0]), "+f"(d[1]), "+f"(d[2]), "+f"(d[3])
        : "r"(a[0]), "r"(a[1]), "r"(a[2]), "r"(a[3]), "r"(b[0]), "r"(b[1]));
}

// ---------------------------------------------------------------------------
// fp32 -> bf16 hi/lo split (elementwise)
// ---------------------------------------------------------------------------
__global__ void split_hi_lo(const float* __restrict__ src,
                            __nv_bfloat16* __restrict__ hi,
                            __nv_bfloat16* __restrict__ lo, size_t n)
{
    size_t stride = (size_t)gridDim.x * blockDim.x * 4;
    for (size_t i = ((size_t)blockIdx.x * blockDim.x + threadIdx.x) * 4; i < n; i += stride) {
        float4 f = *(const float4*)(src + i);
        __nv_bfloat16 h0 = __float2bfloat16(f.x);
        __nv_bfloat16 h1 = __float2bfloat16(f.y);
        __nv_bfloat16 h2 = __float2bfloat16(f.z);
        __nv_bfloat16 h3 = __float2bfloat16(f.w);
        __nv_bfloat16 l0 = __float2bfloat16(f.x - __bfloat162float(h0));
        __nv_bfloat16 l1 = __float2bfloat16(f.y - __bfloat162float(h1));
        __nv_bfloat16 l2 = __float2bfloat16(f.z - __bfloat162float(h2));
        __nv_bfloat16 l3 = __float2bfloat16(f.w - __bfloat162float(h3));
        __nv_bfloat162* ph = (__nv_bfloat162*)(hi + i);
        __nv_bfloat162* pl = (__nv_bfloat162*)(lo + i);
        __nv_bfloat162 a; a.x = h0; a.y = h1; ph[0] = a;
        __nv_bfloat162 b; b.x = h2; b.y = h3; ph[1] = b;
        __nv_bfloat162 c; c.x = l0; c.y = l1; pl[0] = c;
        __nv_bfloat162 d; d.x = l2; d.y = l3; pl[1] = d;
    }
}

// ---------------------------------------------------------------------------
// mma.sync bf16 GEMM (NT): C[M,N] = (Ah+Al)[M,K]*(Bh+Bl)[N,K]^T (3 products)
// 128x128 CTA tile, BK=32, 256 threads = 8 warps (4 along M x 2 along N),
// warp tile 32x64. cp.async 3-stage smem pipeline. Padded smem stride 40 bf16.
// ---------------------------------------------------------------------------
#define SKP 40                      // smem row stride in bf16 (80 bytes)
#define MTILE_B (128 * SKP * 2)     // 10240 bytes per operand tile
#define MBUF_B (4 * MTILE_B)        // Ah,Al,Bh,Bl per stage
#define MSTAGES 3
#define GEMM_SMEM (MSTAGES * MBUF_B)   // 122880 B

__device__ __forceinline__ void issue_stage(
    uint32_t sbase, int stage, int kc,
    const __nv_bfloat16* __restrict__ Ah, const __nv_bfloat16* __restrict__ Al,
    const __nv_bfloat16* __restrict__ Bh, const __nv_bfloat16* __restrict__ Bl,
    size_t rowBase, size_t colBase, int K, int tid)
{
    const int row = tid >> 1;          // 0..127
    const int half = tid & 1;          // 0..1  (32B each)
    const uint32_t dbase = sbase + stage * MBUF_B + row * 80 + half * 32;
    const size_t koff = (size_t)kc * 32;
    {   const char* s = (const char*)(Ah + (rowBase + row) * (size_t)K + koff) + half * 32;
        CP_ASYNC16(dbase + 0 * MTILE_B,      s);
        CP_ASYNC16(dbase + 0 * MTILE_B + 16, s + 16); }
    {   const char* s = (const char*)(Al + (rowBase + row) * (size_t)K + koff) + half * 32;
        CP_ASYNC16(dbase + 1 * MTILE_B,      s);
        CP_ASYNC16(dbase + 1 * MTILE_B + 16, s + 16); }
    {   const char* s = (const char*)(Bh + (colBase + row) * (size_t)K + koff) + half * 32;
        CP_ASYNC16(dbase + 2 * MTILE_B,      s);
        CP_ASYNC16(dbase + 2 * MTILE_B + 16, s + 16); }
    {   const char* s = (const char*)(Bl + (colBase + row) * (size_t)K + koff) + half * 32;
        CP_ASYNC16(dbase + 3 * MTILE_B,      s);
        CP_ASYNC16(dbase + 3 * MTILE_B + 16, s + 16); }
}

__global__ __launch_bounds__(256, 1) void gemm_bf16x3(
    const __nv_bfloat16* __restrict__ Ah, const __nv_bfloat16* __restrict__ Al,
    const __nv_bfloat16* __restrict__ Bh, const __nv_bfloat16* __restrict__ Bl,
    float* __restrict__ C, int M, int N, int K)
{
    extern __shared__ char sm[];
    const uint32_t sb = smem_u32(sm);
    const int tid  = threadIdx.x;
    const int wid  = tid >> 5;
    const int lane = tid & 31;
    const int warpM = wid & 3;          // 4 warps along M
    const int warpN = wid >> 2;         // 2 warps along N

    // CTA -> (mt, nt): groups of 8 M-tiles, n fastest inside a group
    const int NT = N >> 7;
    const int bid = blockIdx.x;
    const int grp = bid / (8 * NT);
    const int rem = bid % (8 * NT);
    const int mt = grp * 8 + (rem & 7);
    const int nt = rem >> 3;
    const size_t rowBase = (size_t)mt * 128;
    const size_t colBase = (size_t)nt * 128;

    float acc[2][8][4];
    #pragma unroll
    for (int i = 0; i < 2; i++)
        #pragma unroll
        for (int j = 0; j < 8; j++)
            #pragma unroll
            for (int k = 0; k < 4; k++) acc[i][j][k] = 0.f;

    // lane-derived ldmatrix row/k offsets
    const int a_row  = lane & 15;            // within 16-row m-tile
    const int a_koff = (lane >> 4) * 8;
    const int b_row  = ((lane >> 4) * 8) + (lane & 7);  // within 16-row n-pair
    const int b_koff = ((lane >> 3) & 1) * 8;

    const int nch = K / 32;
    issue_stage(sb, 0, 0, Ah, Al, Bh, Bl, rowBase, colBase, K, tid); CP_COMMIT();
    issue_stage(sb, 1, 1, Ah, Al, Bh, Bl, rowBase, colBase, K, tid); CP_COMMIT();

    const int atp[3] = {0, 0, 1};
    const int btp[3] = {2, 3, 2};

    for (int i = 0; i < nch; i++) {
        if (i + 1 < nch) { asm volatile("cp.async.wait_group 1;" ::: "memory"); }
        else             { asm volatile("cp.async.wait_group 0;" ::: "memory"); }
        __syncthreads();

        const uint32_t stg = sb + (i % 3) * MBUF_B;
        #pragma unroll
        for (int p = 0; p < 3; p++) {
            const uint32_t Ab = stg + atp[p] * MTILE_B;
            const uint32_t Bb = stg + btp[p] * MTILE_B;
            #pragma unroll
            for (int kk = 0; kk < 32; kk += 16) {
                uint32_t afr[2][4];
                #pragma unroll
                for (int m2 = 0; m2 < 2; m2++) {
                    uint32_t addr = Ab + (warpM * 32 + m2 * 16 + a_row) * 80
                                  + (kk + a_koff) * 2;
                    ldmatrix_x4(afr[m2][0], afr[m2][1], afr[m2][2], afr[m2][3], addr);
                }
                uint32_t bfr[8][2];
                #pragma unroll
                for (int np = 0; np < 4; np++) {
                    uint32_t addr = Bb + (warpN * 64 + np * 16 + b_row) * 80
                                  + (kk + b_koff) * 2;
                    ldmatrix_x4(bfr[np * 2][0], bfr[np * 2][1],
                                bfr[np * 2 + 1][0], bfr[np * 2 + 1][1], addr);
                }
                #pragma unroll
                for (int m2 = 0; m2 < 2; m2++)
                    #pragma unroll
                    for (int n2 = 0; n2 < 8; n2++)
                        mma_bf16(acc[m2][n2], afr[m2], bfr[n2]);
            }
        }
        // issue stage i+2 into buffer (i+2)%3 (its old readers finished at the
        // barrier that opened this iteration)
        if (i + 2 < nch) {
            issue_stage(sb, (i + 2) % 3, i + 2, Ah, Al, Bh, Bl, rowBase, colBase, K, tid);
            CP_COMMIT();
        }
    }

    // epilogue: write fp32 C
    #pragma unroll
    for (int m2 = 0; m2 < 2; m2++) {
        const size_t r0 = rowBase + warpM * 32 + m2 * 16 + (lane >> 2);
        #pragma unroll
        for (int n2 = 0; n2 < 8; n2++) {
            const size_t c0 = colBase + warpN * 64 + n2 * 8 + (lane & 3) * 2;
            float2 v0 = make_float2(acc[m2][n2][0], acc[m2][n2][1]);
            float2 v1 = make_float2(acc[m2][n2][2], acc[m2][n2][3]);
            *(float2*)(C + r0 * (size_t)N + c0)       = v0;
            *(float2*)(C + (r0 + 8) * (size_t)N + c0) = v1;
        }
    }
}

// ---------------------------------------------------------------------------
// RoPE + split/transpose: g_qkv [tok][12288] -> g_q/g_k/g_v [b,h,s,d]
// ---------------------------------------------------------------------------
__global__ void rope_kernel(const int* __restrict__ pos)
{
    const int h = blockIdx.x;
    const int s = blockIdx.y;
    const int b = blockIdx.z;
    const int d = threadIdx.x;          // 0..63

    const size_t tok = (size_t)b * SS + s;
    const float* base = g_qkv + tok * QKVD + (size_t)h * HD;
    const float p = (float)pos[tok];

    const float c0 = 13.287712379549449f / 64.f;   // log2(10000)/64
    float ang = p * exp2f(-(float)d * c0);
    float cs, sn;
    sincosf(ang, &sn, &cs);

    const size_t oidx = (((size_t)(b * NHH + h)) * SS + s) * HD;

    float x1 = base[d], x2 = base[d + 64];
    g_q[oidx + d]      = x1 * cs - x2 * sn;
    g_q[oidx + d + 64] = x2 * cs + x1 * sn;
    x1 = base[HH + d]; x2 = base[HH + d + 64];
    g_k[oidx + d]      = x1 * cs - x2 * sn;
    g_k[oidx + d + 64] = x2 * cs + x1 * sn;
    g_v[oidx + d]      = base[2 * HH + d];
    g_v[oidx + d + 64] = base[2 * HH + d + 64];
}

// ---------------------------------------------------------------------------
// fp32 causal flash attention; epilogue emits bf16 hi/lo for the proj GEMM.
// ---------------------------------------------------------------------------
#define ATTN_SMEM_BYTES ((64*132*2 + 64*68) * 4)

__device__ __forceinline__ uint32_t pack_bf2(float a, float b) {
    __nv_bfloat162 t; t.x = __float2bfloat16(a); t.y = __float2bfloat16(b);
    return *(uint32_t*)&t;
}

__global__ __launch_bounds__(256) void attn_kernel(void)
{
    extern __shared__ float smf[];
    float* Qs  = smf;
    float* KVs = smf + 64 * 132;
    float* Ps  = smf + 2 * 64 * 132;

    const int qt = blockIdx.x;
    const int h  = blockIdx.y;
    const int b  = blockIdx.z;
    const int tid = threadIdx.x;
    const int ty  = tid >> 4;
    const int tx  = tid & 15;

    const size_t headBase = ((size_t)(b * NHH + h)) * SS * HD;
    const float* Qg = g_q + headBase + (size_t)qt * 64 * HD;
    const float* Kg = g_k + headBase;
    const float* Vg = g_v + headBase;

    for (int idx = tid; idx < 64 * 32; idx += 256) {
        int r = idx >> 5, c4 = idx & 31;
        *(float4*)(Qs + r * 132 + c4 * 4) = *(const float4*)(Qg + (size_t)r * HD + c4 * 4);
    }

    float o[4][8];
    float m[4], l[4];
    #pragma unroll
    for (int r = 0; r < 4; r++) {
        m[r] = -1e30f; l[r] = 0.f;
        #pragma unroll
        for (int c = 0; c < 8; c++) o[r][c] = 0.f;
    }

    const int qi0 = qt * 64;
    const float scale = 0.08838834764831845f;

    for (int jt = 0; jt <= qt; jt++) {
        __syncthreads();
        for (int idx = tid; idx < 64 * 32; idx += 256) {
            int r = idx >> 5, c4 = idx & 31;
            *(float4*)(KVs + r * 132 + c4 * 4) =
                *(const float4*)(Kg + ((size_t)(jt * 64 + r)) * HD + c4 * 4);
        }
        __syncthreads();

        float s[4][4];
        #pragma unroll
        for (int r = 0; r < 4; r++)
            #pragma unroll
            for (int c = 0; c < 4; c++) s[r][c] = 0.f;

        #pragma unroll 8
        for (int d = 0; d < 128; d += 4) {
            float4 qv[4], kv[4];
            #pragma unroll
            for (int r = 0; r < 4; r++) qv[r] = *(const float4*)(Qs + (ty * 4 + r) * 132 + d);
            #pragma unroll
            for (int c = 0; c < 4; c++) kv[c] = *(const float4*)(KVs + (tx * 4 + c) * 132 + d);
            #pragma unroll
            for (int r = 0; r < 4; r++)
                #pragma unroll
                for (int c = 0; c < 4; c++) {
                    s[r][c] = fmaf(qv[r].x, kv[c].x, s[r][c]);
                    s[r][c] = fmaf(qv[r].y, kv[c].y, s[r][c]);
                    s[r][c] = fmaf(qv[r].z, kv[c].z, s[r][c]);
                    s[r][c] = fmaf(qv[r].w, kv[c].w, s[r][c]);
                }
        }

        #pragma unroll
        for (int r = 0; r < 4; r++) {
            const int qi = qi0 + ty * 4 + r;
            float mloc = -1e30f;
            #pragma unroll
            for (int c = 0; c < 4; c++) {
                const int kj = jt * 64 + tx * 4 + c;
                float sv = (kj <= qi) ? s[r][c] * scale : -1e30f;
                s[r][c] = sv;
                mloc = fmaxf(mloc, sv);
            }
            #pragma unroll
            for (int off = 8; off >= 1; off >>= 1)
                mloc = fmaxf(mloc, __shfl_xor_sync(0xffffffffu, mloc, off, 16));
            const float mnew = fmaxf(m[r], mloc);
            const float corr = __expf(m[r] - mnew);
            float psum = 0.f;
            #pragma unroll
            for (int c = 0; c < 4; c++) {
                float pv = __expf(s[r][c] - mnew);
                s[r][c] = pv;
                psum += pv;
            }
            #pragma unroll
            for (int off = 8; off >= 1; off >>= 1)
                psum += __shfl_xor_sync(0xffffffffu, psum, off, 16);
            l[r] = l[r] * corr + psum;
            m[r] = mnew;
            #pragma unroll
            for (int c = 0; c < 8; c++) o[r][c] *= corr;
        }

        #pragma unroll
        for (int r = 0; r < 4; r++)
            #pragma unroll
            for (int c = 0; c < 4; c++)
                Ps[(ty * 4 + r) * 68 + tx * 4 + c] = s[r][c];
        __syncthreads();

        for (int idx = tid; idx < 64 * 32; idx += 256) {
            int r = idx >> 5, c4 = idx & 31;
            *(float4*)(KVs + r * 132 + c4 * 4) =
                *(const float4*)(Vg + ((size_t)(jt * 64 + r)) * HD + c4 * 4);
        }
        __syncthreads();

        #pragma unroll 4
        for (int j = 0; j < 64; j++) {
            float pr[4];
            #pragma unroll
            for (int r = 0; r < 4; r++) pr[r] = Ps[(ty * 4 + r) * 68 + j];
            float4 v0 = *(const float4*)(KVs + j * 132 + tx * 8 + 0);
            float4 v1 = *(const float4*)(KVs + j * 132 + tx * 8 + 4);
            #pragma unroll
            for (int r = 0; r < 4; r++) {
                o[r][0] = fmaf(pr[r], v0.x, o[r][0]);
                o[r][1] = fmaf(pr[r], v0.y, o[r][1]);
                o[r][2] = fmaf(pr[r], v0.z, o[r][2]);
                o[r][3] = fmaf(pr[r], v0.w, o[r][3]);
                o[r][4] = fmaf(pr[r], v1.x, o[r][4]);
                o[r][5] = fmaf(pr[r], v1.y, o[r][5]);
                o[r][6] = fmaf(pr[r], v1.z, o[r][6]);
                o[r][7] = fmaf(pr[r], v1.w, o[r][7]);
            }
        }
    }

    // epilogue: normalize, split into bf16 hi/lo, store for proj GEMM
    #pragma unroll
    for (int r = 0; r < 4; r++) {
        const int s_idx = qi0 + ty * 4 + r;
        const float inv = 1.f / l[r];
        const size_t off = ((size_t)(b * SS + s_idx)) * HH + (size_t)h * HD + tx * 8;
        float v[8];
        #pragma unroll
        for (int c = 0; c < 8; c++) v[c] = o[r][c] * inv;
        float hiv[8], lov[8];
        #pragma unroll
        for (int c = 0; c < 8; c++) {
            __nv_bfloat16 hb = __float2bfloat16(v[c]);
            hiv[c] = __bfloat162float(hb);
            lov[c] = v[c] - hiv[c];
        }
        uint4 ph = make_uint4(pack_bf2(hiv[0], hiv[1]), pack_bf2(hiv[2], hiv[3]),
                              pack_bf2(hiv[4], hiv[5]), pack_bf2(hiv[6], hiv[7]));
        uint4 pl = make_uint4(pack_bf2(lov[0], lov[1]), pack_bf2(lov[2], lov[3]),
                              pack_bf2(lov[4], lov[5]), pack_bf2(lov[6], lov[7]));
        *(uint4*)(g_ao_h + off) = ph;
        *(uint4*)(g_ao_l + off) = pl;
    }
}

// ---------------------------------------------------------------------------
// launch
// ---------------------------------------------------------------------------
extern "C" void kernel_launch(void* const* d_in, const int* in_sizes, int n_in,
                              void* d_out, int out_size)
{
    (void)in_sizes; (void)n_in; (void)out_size;
    const float* hidden = (const float*)d_in[0];
    const int*   pos    = (const int*)  d_in[1];
    const float* w_pack = (const float*)d_in[2];
    const float* w_o    = (const float*)d_in[3];
    float* out = (float*)d_out;

    float* p_qkv;
    cudaGetSymbolAddress((void**)&p_qkv, g_qkv);
    __nv_bfloat16 *p_hid_h, *p_hid_l, *p_wp_h, *p_wp_l, *p_wo_h, *p_wo_l, *p_ao_h, *p_ao_l;
    cudaGetSymbolAddress((void**)&p_hid_h, g_hid_h);
    cudaGetSymbolAddress((void**)&p_hid_l, g_hid_l);
    cudaGetSymbolAddress((void**)&p_wp_h,  g_wp_h);
    cudaGetSymbolAddress((void**)&p_wp_l,  g_wp_l);
    cudaGetSymbolAddress((void**)&p_wo_h,  g_wo_h);
    cudaGetSymbolAddress((void**)&p_wo_l,  g_wo_l);
    cudaGetSymbolAddress((void**)&p_ao_h,  g_ao_h);
    cudaGetSymbolAddress((void**)&p_ao_l,  g_ao_l);

    cudaFuncSetAttribute(attn_kernel, cudaFuncAttributeMaxDynamicSharedMemorySize, ATTN_SMEM_BYTES);
    cudaFuncSetAttribute(gemm_bf16x3, cudaFuncAttributeMaxDynamicSharedMemorySize, GEMM_SMEM);

    // 0) fp32 -> bf16 hi/lo splits
    split_hi_lo<<<2048, 256>>>(hidden, p_hid_h, p_hid_l, (size_t)TOK * HH);
    split_hi_lo<<<4096, 256>>>(w_pack, p_wp_h,  p_wp_l,  (size_t)QKVD * HH);
    split_hi_lo<<<2048, 256>>>(w_o,    p_wo_h,  p_wo_l,  (size_t)HH * HH);

    // 1) QKV projection (HMMA): [4096 x 4096] x [12288 x 4096]^T
    {
        int grid = (TOK / 128) * (QKVD / 128);   // 3072
        gemm_bf16x3<<<grid, 256, GEMM_SMEM>>>(p_hid_h, p_hid_l, p_wp_h, p_wp_l,
                                              p_qkv, TOK, QKVD, HH);
    }

    // 2) RoPE + split/transpose
    {
        dim3 grid(NHH, SS, BB);
        rope_kernel<<<grid, 64>>>(pos);
    }

    // 3) causal flash attention (writes bf16 hi/lo directly)
    {
        dim3 grid(SS / 64, NHH, BB);
        attn_kernel<<<grid, 256, ATTN_SMEM_BYTES>>>();
    }

    // 4) output projection (HMMA): [4096 x 4096] x [4096 x 4096]^T -> d_out
    {
        int grid = (TOK / 128) * (HH / 128);     // 1024
        gemm_bf16x3<<<grid, 256, GEMM_SMEM>>>(p_ao_h, p_ao_l, p_wo_h, p_wo_l,
                                              out, TOK, HH, HH);
    }
}